// round 14
// baseline (speedup 1.0000x reference)
#include <cuda_runtime.h>

#define BATCH 16
#define CH    256
#define IH    100
#define IW    100
#define NBOX  100
#define RH    40
#define RW    40
#define NCLS  599
#define CPB   2
#define CTAS_PER_B (CH / CPB)                   // 128

// Scratch (no allocations allowed); zero-initialized at load
__device__ float g_pooled[BATCH * NBOX * CH];   // [B][N][C]
__device__ int   g_start[BATCH * (NCLS + 1)];   // class -> start offset in g_list
__device__ int   g_list[BATCH * NBOX];          // box idx sorted by class (asc n within)
__device__ int   g_scls[BATCH * NBOX];          // class at each sorted position
__device__ int   g_arrive[BATCH];               // arrival counters (reset each launch)
__device__ int   g_flag[BATCH];                 // meta-sort-done flags (reset each launch)

// --- memory-model helpers: release publishes without CCTL.IVALL; .cg reads L2 ---
__device__ __forceinline__ int atom_add_release_gpu(int* p, int v) {
    int old;
    asm volatile("atom.release.gpu.global.add.s32 %0, [%1], %2;"
                 : "=r"(old) : "l"(p), "r"(v) : "memory");
    return old;
}
__device__ __forceinline__ void st_release_gpu(int* p, int v) {
    asm volatile("st.release.gpu.global.s32 [%0], %1;" :: "l"(p), "r"(v) : "memory");
}
__device__ __forceinline__ int ld_cg_i(const int* p) {
    int v;
    asm volatile("ld.global.cg.s32 %0, [%1];" : "=r"(v) : "l"(p) : "memory");
    return v;
}

// Quantize one box to the 40x40 grid (matches jnp.round half-to-even + clip).
__device__ __forceinline__ int quantize_box(float4 bb, bool& valid) {
    const float s = 40.0f / 1024.0f;            // exact in fp32
    int x1 = max((int)rintf(bb.x * s), 0);
    int y1 = max((int)rintf(bb.y * s), 0);
    int x2 = min((int)rintf(bb.z * s), RW);
    int y2 = min((int)rintf(bb.w * s), RH);
    valid = (x1 < x2) && (y1 < y2);
    x1 = min(max(x1, 0), RW);  x2 = min(max(x2, 0), RW);
    y1 = min(max(y1, 0), RH);  y2 = min(max(y2, 0), RH);
    return x1 | (y1 << 8) | (x2 << 16) | (y2 << 24);
}

// ---------------------------------------------------------------------------
// Single fused kernel.
//  main body (all 2048 CTAs): R13's proven resize + pool + pooled write.
//  meta CTA (first blk of batch): counting-sort at START, publish flag.
//  filler CTAs (7 fixed per batch): zero-fill empty-class rows (flag-gated).
//  finisher (128th arriver per batch): write nonempty rows, reset counters.
// ---------------------------------------------------------------------------
__global__ __launch_bounds__(256) void fused_kernel(
        const float* __restrict__ feat, const float* __restrict__ boxes,
        const int* __restrict__ gt, float* __restrict__ out) {
    __shared__ float res[CPB][RH * RW];         // 12.8 KB
    __shared__ int   s_box[NBOX];
    __shared__ float s_pool[NBOX][CPB];
    __shared__ int   s_cls[NBOX];               // meta CTA only
    __shared__ int   s_cnt[NCLS];               // meta CTA only
    __shared__ int   s_blk[20];
    __shared__ int   s_old;

    const int blk    = blockIdx.x;
    const int b      = blk / CTAS_PER_B;
    const int ctaInB = blk % CTAS_PER_B;        // 0..127
    const int cbas   = ctaInB * CPB;
    const int tid    = threadIdx.x;
    const bool meta  = (ctaInB == 0);           // uniform across CTA

    // --- quantize this batch's boxes (threads 0..99) ---
    bool v_me = false;
    if (tid < NBOX) {
        float4 bb = __ldg((const float4*)boxes + b * NBOX + tid);
        int pk = quantize_box(bb, v_me);
        s_box[tid] = v_me ? pk : 0;             // invalid -> x1==x2==0
        if (meta) {
            int cls = __ldg(gt + b * NBOX + tid);
            s_cls[tid] = v_me ? cls : -1;
        }
    }

    // --- meta CTA: counting-sort FIRST (needs only boxes/gt), publish flag ---
    if (meta) {
        __syncthreads();                        // s_cls ready
        for (int i = tid; i < NCLS; i += 256) s_cnt[i] = 0;
        __syncthreads();
        if (tid < NBOX && s_cls[tid] >= 0)
            atomicAdd(&s_cnt[s_cls[tid]], 1);   // histogram
        __syncthreads();
        if (tid < 19) {
            int s = 0;
            for (int j = 0; j < 32; j++) {
                int c = tid * 32 + j;
                if (c < NCLS) s += s_cnt[c];
            }
            s_blk[tid] = s;
        }
        __syncthreads();
        if (tid == 0) {
            int r = 0;
            for (int w = 0; w < 19; w++) { int t = s_blk[w]; s_blk[w] = r; r += t; }
            s_blk[19] = r;                      // total valid boxes
        }
        __syncthreads();
        if (tid < 19) {
            int r = s_blk[tid];
            for (int j = 0; j < 32; j++) {
                int c = tid * 32 + j;
                if (c < NCLS) { int t = s_cnt[c]; s_cnt[c] = r; r += t; }
            }
        }
        __syncthreads();
        for (int i = tid; i < NCLS; i += 256)
            g_start[b * (NCLS + 1) + i] = s_cnt[i];
        if (tid == 0)
            g_start[b * (NCLS + 1) + NCLS] = s_blk[19];
        if (tid < NBOX && s_cls[tid] >= 0) {    // deterministic ascending order
            int c = s_cls[tid];
            int rank = 0;
            for (int m = 0; m < tid; m++) rank += (s_cls[m] == c);
            int pos = s_cnt[c] + rank;
            g_list[b * NBOX + pos] = tid;
            g_scls[b * NBOX + pos] = c;
        }
        __syncthreads();                        // sort writes issued by all threads
        if (tid == 0) st_release_gpu(&g_flag[b], 1);   // publish (no L1 flush)
    }

    // --- bilinear resize (half-pixel centers): src = 2.5*dst + 0.75 ---
    const float* __restrict__ in0 = feat + (size_t)(b * CH + cbas) * (IH * IW);
    const float* __restrict__ in1 = in0 + IH * IW;
    for (int i = tid; i < RH * RW; i += 256) {
        int oy = i / RW, ox = i % RW;
        float sy = 2.5f * (float)oy + 0.75f;    // frac is exactly .75 or .25
        float sx = 2.5f * (float)ox + 0.75f;
        int y0 = (int)sy;  float fy = sy - (float)y0;
        int x0 = (int)sx;  float fx = sx - (float)x0;
        int off = y0 * IW + x0;
        float gx0 = 1.0f - fx, gy0 = 1.0f - fy;
        float a00 = __ldg(in0 + off),      a01 = __ldg(in0 + off + 1);
        float a10 = __ldg(in0 + off + IW), a11 = __ldg(in0 + off + IW + 1);
        float b00 = __ldg(in1 + off),      b01 = __ldg(in1 + off + 1);
        float b10 = __ldg(in1 + off + IW), b11 = __ldg(in1 + off + IW + 1);
        res[0][i] = gy0 * (gx0 * a00 + fx * a01) + fy * (gx0 * a10 + fx * a11);
        res[1][i] = gy0 * (gx0 * b00 + fx * b01) + fy * (gx0 * b10 + fx * b11);
    }
    __syncthreads();

    // --- direct box-average pooling: thread = (plane, box) ---
    if (tid < NBOX * CPB) {
        int n = tid % NBOX;
        int p = tid / NBOX;
        int pk = s_box[n];
        int x1 = pk & 0xFF, y1 = (pk >> 8) & 0xFF;
        int x2 = (pk >> 16) & 0xFF, y2 = (pk >> 24) & 0xFF;
        float ov = 0.0f;
        if (x1 < x2) {
            float s = 0.0f;
            const float* r = res[p];
            for (int y = y1; y < y2; y++) {
                float rs = 0.0f;
                for (int x = x1; x < x2; x++) rs += r[y * RW + x];
                s += rs;
            }
            ov = s / (float)((y2 - y1) * (x2 - x1));
        }
        s_pool[n][p] = ov;
    }
    __syncthreads();

    // --- transposed write: one float2 per box into [B][N][C] ---
    if (tid < NBOX) {
        float2 v2 = make_float2(s_pool[tid][0], s_pool[tid][1]);
        *(float2*)(g_pooled + (size_t)(b * NBOX + tid) * CH + cbas) = v2;
    }

    // --- filler CTAs: zero-fill empty-class rows of this batch's output ---
    // 7 fixed CTAs per batch (ctaInB = 16,32,...,112); slice s in 0..6 covers
    // classes c ≡ s (mod 7). Depends ONLY on meta's sort (flag ~always set:
    // meta is the first CTA of the batch to launch).
    if (ctaInB != 0 && (ctaInB & 15) == 0 && (ctaInB >> 4) <= 7) {
        while (ld_cg_i(&g_flag[b]) == 0) { }    // ~0 iterations in practice
        const int s   = (ctaInB >> 4) - 1;      // 0..6
        const int grp = tid >> 6;               // 4 groups of 64 threads
        const int q   = tid & 63;               // float4 slot in row
        const int* sb = &g_start[b * (NCLS + 1)];
        const float4 z = make_float4(0.0f, 0.0f, 0.0f, 0.0f);
        for (int ci = grp; s + 7 * ci < NCLS; ci += 4) {
            int c  = s + 7 * ci;
            int st = ld_cg_i(sb + c);
            int en = ld_cg_i(sb + c + 1);
            if (en == st)                       // empty class -> zeros
                ((float4*)(out + (size_t)(b * NCLS + c) * CH))[q] = z;
        }
    }

    // --- arrival: release-publish this CTA's writes; last arriver finishes ---
    __syncthreads();
    if (tid == 0) s_old = atom_add_release_gpu(&g_arrive[b], 1);
    __syncthreads();
    if (s_old != CTAS_PER_B - 1) return;

    // Finisher: all 128 CTAs of batch b done -> pooled data in L2 (.cg reads).
    const int wid  = tid >> 5;                  // 8 independent warps
    const int lane = tid & 31;
    const int* sb  = &g_start[b * (NCLS + 1)];
    const int total = ld_cg_i(sb + NCLS);

    for (int k = wid; k < total; k += 8) {
        int cls = ld_cg_i(&g_scls[b * NBOX + k]);
        int st  = ld_cg_i(sb + cls);
        if (k != st) continue;                  // not a segment head
        int en  = ld_cg_i(sb + cls + 1);
        float4 a0 = make_float4(0.f, 0.f, 0.f, 0.f);
        float4 a1 = make_float4(0.f, 0.f, 0.f, 0.f);
        for (int j = st; j < en; j++) {         // ascending n == segment_sum order
            int n = ld_cg_i(&g_list[b * NBOX + j]);
            const float4* row = (const float4*)(g_pooled + (size_t)(b * NBOX + n) * CH);
            float4 v0 = __ldcg(row + lane);
            float4 v1 = __ldcg(row + lane + 32);
            a0.x += v0.x; a0.y += v0.y; a0.z += v0.z; a0.w += v0.w;
            a1.x += v1.x; a1.y += v1.y; a1.z += v1.z; a1.w += v1.w;
        }
        float inv = 1.0f / (float)(en - st);
        a0.x *= inv; a0.y *= inv; a0.z *= inv; a0.w *= inv;
        a1.x *= inv; a1.y *= inv; a1.z *= inv; a1.w *= inv;
        float4* o = (float4*)(out + (size_t)(b * NCLS + cls) * CH);
        o[lane]      = a0;
        o[lane + 32] = a1;
    }

    if (tid == 0) {                             // reset for next graph replay
        g_arrive[b] = 0;
        g_flag[b]   = 0;
    }
}

// ---------------------------------------------------------------------------
extern "C" void kernel_launch(void* const* d_in, const int* in_sizes, int n_in,
                              void* d_out, int out_size) {
    const float* feat  = (const float*)d_in[0];   // [16,256,100,100] f32
    const float* boxes = (const float*)d_in[1];   // [16,100,4] f32
    const int*   gt    = (const int*)d_in[2];     // [16,100] i32
    float* out = (float*)d_out;                   // [16,599,256] f32

    fused_kernel<<<BATCH * CTAS_PER_B, 256>>>(feat, boxes, gt, out);
}

// round 15
// speedup vs baseline: 1.5125x; 1.5125x over previous
#include <cuda_runtime.h>

#define BATCH 16
#define CH    256
#define IH    100
#define IW    100
#define NBOX  100
#define RH    40
#define RW    40
#define NCLS  599
#define CPB   2          // channels per CTA in resize/pool kernel (known-good)

// Scratch (no allocations allowed)
__device__ float g_pooled[BATCH * NBOX * CH];   // [B][N][C]  (coalesced reads in k2)
__device__ int   g_start[BATCH * (NCLS + 1)];   // class -> start offset in g_list
__device__ int   g_list[BATCH * NBOX];          // box idx sorted by class (asc n within)

// Quantize one box (xyxy, image coords) to the 40x40 grid. Matches
// jnp.round (half-to-even) + clip semantics of the reference.
__device__ __forceinline__ int quantize_box(float4 bb, bool& valid) {
    const float s = 40.0f / 1024.0f;            // exact in fp32
    int x1 = max((int)rintf(bb.x * s), 0);
    int y1 = max((int)rintf(bb.y * s), 0);
    int x2 = min((int)rintf(bb.z * s), RW);
    int y2 = min((int)rintf(bb.w * s), RH);
    valid = (x1 < x2) && (y1 < y2);
    x1 = min(max(x1, 0), RW);  x2 = min(max(x2, 0), RW);
    y1 = min(max(y1, 0), RH);  y2 = min(max(y2, 0), RH);
    return x1 | (y1 << 8) | (x2 << 16) | (y2 << 24);
}

// ---------------------------------------------------------------------------
// Kernel 1 (R13-measured best, ~27.6us — UNchanged): per (b, 2 channels) —
// direct-__ldg bilinear 100->40 resize into smem, then direct box-sum pooling.
// The cbas==0 CTA of each batch also counting-sorts boxes by class into
// g_start / g_list (deterministic, ascending-n within each class).
// ---------------------------------------------------------------------------
__global__ __launch_bounds__(256) void resize_pool_kernel(
        const float* __restrict__ feat, const float* __restrict__ boxes,
        const int* __restrict__ gt) {
    __shared__ float res[CPB][RH * RW];         // 12.8 KB
    __shared__ int   s_box[NBOX];               // packed x1,y1,x2,y2 (0 if invalid)
    __shared__ float s_pool[NBOX][CPB];         // staged for float2 writes
    __shared__ int   s_cls[NBOX];               // valid ? cls : -1 (meta CTA)
    __shared__ int   s_cnt[NCLS];               // histogram -> offsets (meta CTA)
    __shared__ int   s_blk[20];

    const int blk  = blockIdx.x;                // 0 .. BATCH*CH/CPB-1
    const int b    = blk / (CH / CPB);
    const int cbas = (blk % (CH / CPB)) * CPB;
    const int tid  = threadIdx.x;
    const bool meta = (cbas == 0);              // uniform across CTA

    // --- quantize this batch's boxes (threads 0..99) ---
    bool v_me = false;
    if (tid < NBOX) {
        float4 bb = __ldg((const float4*)boxes + b * NBOX + tid);
        int pk = quantize_box(bb, v_me);
        s_box[tid] = v_me ? pk : 0;             // invalid -> x1==x2==0
        if (meta) {
            int cls = __ldg(gt + b * NBOX + tid);
            s_cls[tid] = v_me ? cls : -1;
        }
    }

    // --- bilinear resize (half-pixel centers): src = 2.5*dst + 0.75 ---
    const float* __restrict__ in0 = feat + (size_t)(b * CH + cbas) * (IH * IW);
    const float* __restrict__ in1 = in0 + IH * IW;
    for (int i = tid; i < RH * RW; i += 256) {
        int oy = i / RW, ox = i % RW;
        float sy = 2.5f * (float)oy + 0.75f;    // frac is exactly .75 or .25
        float sx = 2.5f * (float)ox + 0.75f;
        int y0 = (int)sy;  float fy = sy - (float)y0;
        int x0 = (int)sx;  float fx = sx - (float)x0;
        int off = y0 * IW + x0;
        float gx0 = 1.0f - fx, gy0 = 1.0f - fy;
        float a00 = __ldg(in0 + off),      a01 = __ldg(in0 + off + 1);
        float a10 = __ldg(in0 + off + IW), a11 = __ldg(in0 + off + IW + 1);
        float b00 = __ldg(in1 + off),      b01 = __ldg(in1 + off + 1);
        float b10 = __ldg(in1 + off + IW), b11 = __ldg(in1 + off + IW + 1);
        res[0][i] = gy0 * (gx0 * a00 + fx * a01) + fy * (gx0 * a10 + fx * a11);
        res[1][i] = gy0 * (gx0 * b00 + fx * b01) + fy * (gx0 * b10 + fx * b11);
    }
    __syncthreads();

    // --- direct box-average pooling: thread = (plane, box) ---
    if (tid < NBOX * CPB) {
        int n = tid % NBOX;
        int p = tid / NBOX;
        int pk = s_box[n];
        int x1 = pk & 0xFF, y1 = (pk >> 8) & 0xFF;
        int x2 = (pk >> 16) & 0xFF, y2 = (pk >> 24) & 0xFF;
        float out = 0.0f;
        if (x1 < x2) {                          // valid (invalid stored as 0)
            float s = 0.0f;
            const float* r = res[p];
            for (int y = y1; y < y2; y++) {
                float rs = 0.0f;
                for (int x = x1; x < x2; x++) rs += r[y * RW + x];
                s += rs;
            }
            out = s / (float)((y2 - y1) * (x2 - x1));
        }
        s_pool[n][p] = out;
    }
    __syncthreads();

    // --- transposed write: one float2 per box into [B][N][C] ---
    if (tid < NBOX) {
        float2 v2 = make_float2(s_pool[tid][0], s_pool[tid][1]);
        *(float2*)(g_pooled + (size_t)(b * NBOX + tid) * CH + cbas) = v2;
    }

    // --- meta CTA only: counting-sort boxes by class (deterministic) ---
    if (meta) {
        for (int i = tid; i < NCLS; i += 256) s_cnt[i] = 0;
        __syncthreads();
        if (tid < NBOX && s_cls[tid] >= 0)
            atomicAdd(&s_cnt[s_cls[tid]], 1);   // histogram
        __syncthreads();
        if (tid < 19) {                          // group sums (19 x 32)
            int s = 0;
            for (int j = 0; j < 32; j++) {
                int c = tid * 32 + j;
                if (c < NCLS) s += s_cnt[c];
            }
            s_blk[tid] = s;
        }
        __syncthreads();
        if (tid == 0) {
            int r = 0;
            for (int w = 0; w < 19; w++) { int t = s_blk[w]; s_blk[w] = r; r += t; }
            s_blk[19] = r;                      // total valid boxes
        }
        __syncthreads();
        if (tid < 19) {
            int r = s_blk[tid];
            for (int j = 0; j < 32; j++) {
                int c = tid * 32 + j;
                if (c < NCLS) { int t = s_cnt[c]; s_cnt[c] = r; r += t; }  // -> offsets
            }
        }
        __syncthreads();
        for (int i = tid; i < NCLS; i += 256)
            g_start[b * (NCLS + 1) + i] = s_cnt[i];
        if (tid == 0)
            g_start[b * (NCLS + 1) + NCLS] = s_blk[19];
        // scatter: rank = #{m<n with same class} (deterministic ascending order)
        if (tid < NBOX && s_cls[tid] >= 0) {
            int c = s_cls[tid];
            int rank = 0;
            for (int m = 0; m < tid; m++) rank += (s_cls[m] == c);
            g_list[b * NBOX + s_cnt[c] + rank] = tid;
        }
    }
}

// ---------------------------------------------------------------------------
// Kernel 2 (R13-measured best, ~7.4us) + PDL: launched with programmatic
// stream serialization so its grid rollout overlaps kernel 1's tail.
// cudaGridDependencySynchronize() blocks each CTA until kernel 1 completes,
// BEFORE any dependent data is read. Work is unchanged: one 64-thread group
// per class; empty class -> STG.128 zeros; non-empty -> walk presorted
// g_list segment (ascending n == segment_sum order) with float4 gathers.
// ---------------------------------------------------------------------------
__global__ __launch_bounds__(256) void class_mean_kernel(float* __restrict__ out) {
    const int t   = threadIdx.x;
    const int cls = blockIdx.x * 4 + (t >> 6);   // class for this 64-thread group
    const int q   = t & 63;                      // channel quad 0..63
    const int b   = blockIdx.y;

    cudaGridDependencySynchronize();             // wait for kernel 1 (PDL)

    if (cls >= NCLS) return;

    const int* sp = &g_start[b * (NCLS + 1) + cls];
    int st = __ldg(sp);                          // uniform broadcast within group
    int en = __ldg(sp + 1);

    float4 acc = make_float4(0.0f, 0.0f, 0.0f, 0.0f);
    if (en > st) {
        const float4* __restrict__ pool =
            (const float4*)(g_pooled + (size_t)b * NBOX * CH) + q;
        for (int k = st; k < en; k++) {          // ascending n within class
            int n = __ldg(&g_list[b * NBOX + k]);
            float4 v = __ldg(pool + (size_t)n * (CH / 4));
            acc.x += v.x;  acc.y += v.y;  acc.z += v.z;  acc.w += v.w;
        }
        float inv = 1.0f / (float)(en - st);
        acc.x *= inv;  acc.y *= inv;  acc.z *= inv;  acc.w *= inv;
    }
    ((float4*)(out + (size_t)(b * NCLS + cls) * CH))[q] = acc;
}

// ---------------------------------------------------------------------------
extern "C" void kernel_launch(void* const* d_in, const int* in_sizes, int n_in,
                              void* d_out, int out_size) {
    const float* feat  = (const float*)d_in[0];   // [16,256,100,100] f32
    const float* boxes = (const float*)d_in[1];   // [16,100,4] f32
    const int*   gt    = (const int*)d_in[2];     // [16,100] i32
    float* out = (float*)d_out;                   // [16,599,256] f32

    resize_pool_kernel<<<BATCH * (CH / CPB), 256>>>(feat, boxes, gt);

    // PDL launch: k2's setup/rollout overlaps k1's tail; correctness is
    // guaranteed by cudaGridDependencySynchronize() inside k2.
    cudaLaunchConfig_t cfg = {};
    cfg.gridDim  = dim3((NCLS + 3) / 4, BATCH);   // 150 x 16
    cfg.blockDim = dim3(256, 1, 1);
    cfg.dynamicSmemBytes = 0;
    cfg.stream = 0;                               // same (legacy) stream as k1
    cudaLaunchAttribute attrs[1];
    attrs[0].id = cudaLaunchAttributeProgrammaticStreamSerialization;
    attrs[0].val.programmaticStreamSerializationAllowed = 1;
    cfg.attrs = attrs;
    cfg.numAttrs = 1;
    cudaLaunchKernelEx(&cfg, class_mean_kernel, (float*)out);
}

// round 16
// speedup vs baseline: 1.5690x; 1.0373x over previous
#include <cuda_runtime.h>

#define BATCH 16
#define CH    256
#define IH    100
#define IW    100
#define NBOX  100
#define RH    40
#define RW    40
#define NCLS  599
#define CPB   2          // channels per CTA in resize/pool kernel (known-good)

// Scratch (no allocations allowed)
__device__ float g_pooled[BATCH * NBOX * CH];   // [B][N][C]  (coalesced reads in k2)
__device__ int2  g_seg[BATCH * NCLS];           // per-class (start, end) into g_list
__device__ int   g_list[BATCH * NBOX];          // box idx sorted by class (asc n within)

// Quantize one box (xyxy, image coords) to the 40x40 grid. Matches
// jnp.round (half-to-even) + clip semantics of the reference.
__device__ __forceinline__ int quantize_box(float4 bb, bool& valid) {
    const float s = 40.0f / 1024.0f;            // exact in fp32
    int x1 = max((int)rintf(bb.x * s), 0);
    int y1 = max((int)rintf(bb.y * s), 0);
    int x2 = min((int)rintf(bb.z * s), RW);
    int y2 = min((int)rintf(bb.w * s), RH);
    valid = (x1 < x2) && (y1 < y2);
    x1 = min(max(x1, 0), RW);  x2 = min(max(x2, 0), RW);
    y1 = min(max(y1, 0), RH);  y2 = min(max(y2, 0), RH);
    return x1 | (y1 << 8) | (x2 << 16) | (y2 << 24);
}

// ---------------------------------------------------------------------------
// Kernel 1 (R13 structure, micro-opt): per (b, 2 channels) — bilinear 100->40
// resize into smem (streaming __ldcs loads — data is strictly single-use),
// integer-exact tap indices/weights, then direct box-sum pooling. The cbas==0
// CTA of each batch also counting-sorts boxes by class into g_seg / g_list
// (deterministic, ascending-n within each class).
// ---------------------------------------------------------------------------
__global__ __launch_bounds__(256) void resize_pool_kernel(
        const float* __restrict__ feat, const float* __restrict__ boxes,
        const int* __restrict__ gt) {
    __shared__ float res[CPB][RH * RW];         // 12.8 KB
    __shared__ int   s_box[NBOX];               // packed x1,y1,x2,y2 (0 if invalid)
    __shared__ float s_pool[NBOX][CPB];         // staged for float2 writes
    __shared__ int   s_cls[NBOX];               // valid ? cls : -1 (meta CTA)
    __shared__ int   s_cnt[NCLS];               // histogram -> offsets (meta CTA)
    __shared__ int   s_blk[20];

    const int blk  = blockIdx.x;                // 0 .. BATCH*CH/CPB-1
    const int b    = blk / (CH / CPB);
    const int cbas = (blk % (CH / CPB)) * CPB;
    const int tid  = threadIdx.x;
    const bool meta = (cbas == 0);              // uniform across CTA

    // --- quantize this batch's boxes (threads 0..99) ---
    bool v_me = false;
    if (tid < NBOX) {
        float4 bb = __ldg((const float4*)boxes + b * NBOX + tid);
        int pk = quantize_box(bb, v_me);
        s_box[tid] = v_me ? pk : 0;             // invalid -> x1==x2==0
        if (meta) {
            int cls = __ldg(gt + b * NBOX + tid);
            s_cls[tid] = v_me ? cls : -1;
        }
    }

    // --- bilinear resize: src = 2.5*dst + 0.75 -> integer-exact taps:
    //     t0 = (5*t+1)>>1 ; frac = t odd ? 0.25 : 0.75 (bit-identical) ---
    const float* __restrict__ in0 = feat + (size_t)(b * CH + cbas) * (IH * IW);
    const float* __restrict__ in1 = in0 + IH * IW;
    for (int i = tid; i < RH * RW; i += 256) {
        int oy = i / RW, ox = i % RW;
        int y0 = (5 * oy + 1) >> 1;
        int x0 = (5 * ox + 1) >> 1;
        float fy = (oy & 1) ? 0.25f : 0.75f;
        float fx = (ox & 1) ? 0.25f : 0.75f;
        int off = y0 * IW + x0;
        float gx0 = 1.0f - fx, gy0 = 1.0f - fy;
        float a00 = __ldcs(in0 + off),      a01 = __ldcs(in0 + off + 1);
        float a10 = __ldcs(in0 + off + IW), a11 = __ldcs(in0 + off + IW + 1);
        float b00 = __ldcs(in1 + off),      b01 = __ldcs(in1 + off + 1);
        float b10 = __ldcs(in1 + off + IW), b11 = __ldcs(in1 + off + IW + 1);
        res[0][i] = gy0 * (gx0 * a00 + fx * a01) + fy * (gx0 * a10 + fx * a11);
        res[1][i] = gy0 * (gx0 * b00 + fx * b01) + fy * (gx0 * b10 + fx * b11);
    }
    __syncthreads();

    // --- direct box-average pooling: thread = (plane, box) ---
    if (tid < NBOX * CPB) {
        int n = tid % NBOX;
        int p = tid / NBOX;
        int pk = s_box[n];
        int x1 = pk & 0xFF, y1 = (pk >> 8) & 0xFF;
        int x2 = (pk >> 16) & 0xFF, y2 = (pk >> 24) & 0xFF;
        float out = 0.0f;
        if (x1 < x2) {                          // valid (invalid stored as 0)
            float s = 0.0f;
            const float* r = res[p];
            for (int y = y1; y < y2; y++) {
                float rs = 0.0f;
                for (int x = x1; x < x2; x++) rs += r[y * RW + x];
                s += rs;
            }
            out = s / (float)((y2 - y1) * (x2 - x1));
        }
        s_pool[n][p] = out;
    }
    __syncthreads();

    // --- transposed write: one float2 per box into [B][N][C] ---
    if (tid < NBOX) {
        float2 v2 = make_float2(s_pool[tid][0], s_pool[tid][1]);
        *(float2*)(g_pooled + (size_t)(b * NBOX + tid) * CH + cbas) = v2;
    }

    // --- meta CTA only: counting-sort boxes by class (deterministic) ---
    if (meta) {
        for (int i = tid; i < NCLS; i += 256) s_cnt[i] = 0;
        __syncthreads();
        if (tid < NBOX && s_cls[tid] >= 0)
            atomicAdd(&s_cnt[s_cls[tid]], 1);   // histogram
        __syncthreads();
        if (tid < 19) {                          // group sums (19 x 32)
            int s = 0;
            for (int j = 0; j < 32; j++) {
                int c = tid * 32 + j;
                if (c < NCLS) s += s_cnt[c];
            }
            s_blk[tid] = s;
        }
        __syncthreads();
        if (tid == 0) {
            int r = 0;
            for (int w = 0; w < 19; w++) { int t = s_blk[w]; s_blk[w] = r; r += t; }
            s_blk[19] = r;                      // total valid boxes
        }
        __syncthreads();
        if (tid < 19) {
            int r = s_blk[tid];
            for (int j = 0; j < 32; j++) {
                int c = tid * 32 + j;
                if (c < NCLS) { int t = s_cnt[c]; s_cnt[c] = r; r += t; }  // -> offsets
            }
        }
        __syncthreads();
        // per-class (start, end) pairs -> one LDG.64 in kernel 2
        for (int c = tid; c < NCLS; c += 256) {
            int st = s_cnt[c];
            int en = (c + 1 < NCLS) ? s_cnt[c + 1] : s_blk[19];
            g_seg[b * NCLS + c] = make_int2(st, en);
        }
        // scatter: rank = #{m<n with same class} (deterministic ascending order)
        if (tid < NBOX && s_cls[tid] >= 0) {
            int c = s_cls[tid];
            int rank = 0;
            for (int m = 0; m < tid; m++) rank += (s_cls[m] == c);
            g_list[b * NBOX + s_cnt[c] + rank] = tid;
        }
    }
}

// ---------------------------------------------------------------------------
// Kernel 2 (R13-measured best shape): scatter-mean, barrier-free. One
// 64-thread group per class (4 per CTA, grid 150x16); thread = float4
// channel-quad. Single LDG.64 fetches (start,end). Empty class (84%): that
// load + one STG.128 of zeros. Non-empty: walk the presorted g_list segment
// (ascending n == segment_sum order) with float4 gathers.
// ---------------------------------------------------------------------------
__global__ __launch_bounds__(256) void class_mean_kernel(float* __restrict__ out) {
    const int t   = threadIdx.x;
    const int cls = blockIdx.x * 4 + (t >> 6);   // class for this 64-thread group
    const int q   = t & 63;                      // channel quad 0..63
    const int b   = blockIdx.y;
    if (cls >= NCLS) return;

    int2 se = __ldg(&g_seg[b * NCLS + cls]);     // one 8B broadcast load
    int st = se.x, en = se.y;

    float4 acc = make_float4(0.0f, 0.0f, 0.0f, 0.0f);
    if (en > st) {
        const float4* __restrict__ pool =
            (const float4*)(g_pooled + (size_t)b * NBOX * CH) + q;
        for (int k = st; k < en; k++) {          // ascending n within class
            int n = __ldg(&g_list[b * NBOX + k]);
            float4 v = __ldg(pool + (size_t)n * (CH / 4));
            acc.x += v.x;  acc.y += v.y;  acc.z += v.z;  acc.w += v.w;
        }
        float inv = 1.0f / (float)(en - st);
        acc.x *= inv;  acc.y *= inv;  acc.z *= inv;  acc.w *= inv;
    }
    ((float4*)(out + (size_t)(b * NCLS + cls) * CH))[q] = acc;
}

// ---------------------------------------------------------------------------
extern "C" void kernel_launch(void* const* d_in, const int* in_sizes, int n_in,
                              void* d_out, int out_size) {
    const float* feat  = (const float*)d_in[0];   // [16,256,100,100] f32
    const float* boxes = (const float*)d_in[1];   // [16,100,4] f32
    const int*   gt    = (const int*)d_in[2];     // [16,100] i32
    float* out = (float*)d_out;                   // [16,599,256] f32

    resize_pool_kernel<<<BATCH * (CH / CPB), 256>>>(feat, boxes, gt);
    dim3 g2((NCLS + 3) / 4, BATCH);               // 150 x 16
    class_mean_kernel<<<g2, 256>>>(out);
}